// round 5
// baseline (speedup 1.0000x reference)
#include <cuda_runtime.h>
#include <cuda_bf16.h>
#include <stdint.h>

// ============================================================================
// BFP8 quantized 3x3 conv (stride 1, pad 1) == GEMM M=100352, N=256, K=1152
// Round 5: single fused kernel, warp-specialized:
//   - 512 consumer threads (16 warps): 4-deep pipelined bf16 mma.sync GEMM
//   - 64 producer threads (2 warps): im2col gather + BFP quantize -> SMEM A,
//     plus cp.async of quantized W -> SMEM B. No DRAM scratch for A.
// Stage = one 64-wide BFP block (CHUNK_K = 64). Named-barrier handshake.
// ============================================================================

#define C_IN      128
#define C_OUT     256
#define HWDIM     56
#define IMG_PIX   3136
#define K_TOTAL   1152
#define M_TOTAL   100352
#define GRID_M    784

#define NCONS     512
#define NPROD     64
#define NTHREADS  (NCONS + NPROD)     // 576

#define CHUNK_K   64
#define NUM_KB    18                  // 1152 / 64
#define NSTAGES   4
#define A_SZ      16384               // 128 rows * 128B (64 bf16)
#define B_SZ      32768               // 256 rows * 128B
#define STAGE_SZ  (A_SZ + B_SZ)       // 49152
#define SMEM_TOTAL (NSTAGES * STAGE_SZ)  // 196608
#define C_STRIDE  132

__device__ __align__(16) __nv_bfloat16 g_wq[C_OUT * K_TOTAL];

// ---------------------------------------------------------------------------
__device__ __forceinline__ uint32_t cvta_smem(const void* p) {
    uint32_t a;
    asm("{ .reg .u64 t; cvta.to.shared.u64 t, %1; cvt.u32.u64 %0, t; }"
        : "=r"(a) : "l"(p));
    return a;
}
__device__ __forceinline__ void ldsm_x4(uint32_t* d, uint32_t addr) {
    asm volatile("ldmatrix.sync.aligned.m8n8.x4.shared.b16 {%0,%1,%2,%3}, [%4];"
                 : "=r"(d[0]), "=r"(d[1]), "=r"(d[2]), "=r"(d[3]) : "r"(addr));
}
__device__ __forceinline__ void mma_16816(float* c, const uint32_t* a,
                                          uint32_t b0, uint32_t b1) {
    asm volatile(
        "mma.sync.aligned.m16n8k16.row.col.f32.bf16.bf16.f32 "
        "{%0,%1,%2,%3}, {%4,%5,%6,%7}, {%8,%9}, {%0,%1,%2,%3};"
        : "+f"(c[0]), "+f"(c[1]), "+f"(c[2]), "+f"(c[3])
        : "r"(a[0]), "r"(a[1]), "r"(a[2]), "r"(a[3]), "r"(b0), "r"(b1));
}
__device__ __forceinline__ void cp_async16(uint32_t dst, const void* src) {
    asm volatile("cp.async.cg.shared.global [%0], [%1], 16;" :: "r"(dst), "l"(src));
}
__device__ __forceinline__ void cp_commit() {
    asm volatile("cp.async.commit_group;");
}
template <int N>
__device__ __forceinline__ void cp_wait() {
    asm volatile("cp.async.wait_group %0;" :: "n"(N));
}
__device__ __forceinline__ void bar_sync(int id, int cnt) {
    asm volatile("bar.sync %0, %1;" :: "r"(id), "r"(cnt) : "memory");
}
__device__ __forceinline__ void bar_arrive(int id, int cnt) {
    asm volatile("bar.arrive %0, %1;" :: "r"(id), "r"(cnt) : "memory");
}
__device__ __forceinline__ void membar_cta() {
    asm volatile("membar.cta;" ::: "memory");
}

__device__ __forceinline__ int block_exp(float mx) {
    mx = fmaxf(mx, 1e-38f);
    return ((__float_as_int(mx) >> 23) & 255) - 127;
}
__device__ __forceinline__ float bfpq(float x, float inv, float scale) {
    float q = rintf(x * inv);
    q = fminf(q, 127.0f);      // round of |x|<=2^(e+1) can't go below -128
    return q * scale;
}

// ---------------------------------------------------------------------------
// Kernel 0: quantize weight -> bf16 g_wq
// ---------------------------------------------------------------------------
__global__ void quant_w_kernel(const float* __restrict__ w) {
    int row = blockIdx.y, blk = blockIdx.x, lane = threadIdx.x;
    int base = row * K_TOTAL + blk * 64;
    float a = w[base + lane];
    float b = w[base + 32 + lane];
    float mx = fmaxf(fabsf(a), fabsf(b));
#pragma unroll
    for (int o = 16; o > 0; o >>= 1)
        mx = fmaxf(mx, __shfl_xor_sync(0xFFFFFFFFu, mx, o));
    int e = block_exp(mx);
    float scale = __int_as_float((e + 121) << 23);
    float inv   = __int_as_float((133 - e) << 23);
    g_wq[base + lane]      = __float2bfloat16(bfpq(a, inv, scale));
    g_wq[base + 32 + lane] = __float2bfloat16(bfpq(b, inv, scale));
}

// ---------------------------------------------------------------------------
// gather one 64-k BFP block of row; S = tap phase (compile-time)
// ---------------------------------------------------------------------------
template <int S>
__device__ __forceinline__ void gather64(const float* __restrict__ pix,
                                         uint32_t vmask, float* v, float& mx) {
#pragma unroll
    for (int e = 0; e < 64; ++e) {
        const int u   = S + e;
        const int ci  = u / 9;
        const int tap = u % 9;
        const int off = ci * IMG_PIX + (tap / 3) * HWDIM + (tap % 3);
        float val = ((vmask >> tap) & 1u) ? __ldg(pix + off) : 0.0f;
        v[e] = val;
        mx = fmaxf(mx, fabsf(val));
    }
}

// ---------------------------------------------------------------------------
// Fused kernel. Grid 784, 576 threads.
// ---------------------------------------------------------------------------
__global__ __launch_bounds__(NTHREADS, 1)
void conv_fused_kernel(const float* __restrict__ inp,
                       const float* __restrict__ bias,
                       float* __restrict__ out) {
    extern __shared__ __align__(16) char smem[];
    const uint32_t smem_u = cvta_smem(smem);
    const int tid = threadIdx.x;
    const int m_base = blockIdx.x * 128;

    if (tid >= NCONS) {
        // ==================== PRODUCER (2 warps, 64 threads) ================
        const int p = tid - NCONS;          // 0..63, owns rows p and p+64

        // per-row identity
        const float* pbase[2];
        uint32_t vmask[2];
#pragma unroll
        for (int h = 0; h < 2; ++h) {
            int r  = p + h * 64;
            int m  = m_base + r;
            int ni = m / IMG_PIX;
            int pp = m - ni * IMG_PIX;
            int ho = pp / HWDIM;
            int wo = pp - ho * HWDIM;
            pbase[h] = inp + (size_t)ni * C_IN * IMG_PIX + ho * HWDIM + wo - 57;
            uint32_t vm = 0;
#pragma unroll
            for (int kh = 0; kh < 3; ++kh)
#pragma unroll
                for (int kw = 0; kw < 3; ++kw) {
                    int hh = ho + kh - 1, ww = wo + kw - 1;
                    if ((unsigned)hh < (unsigned)HWDIM && (unsigned)ww < (unsigned)HWDIM)
                        vm |= 1u << (kh * 3 + kw);
                }
            vmask[h] = vm;
        }

        for (int kc = 0; kc < NUM_KB; ++kc) {
            const int s = kc & 3;
            const uint32_t st = smem_u + s * STAGE_SZ;
            if (kc >= NSTAGES) bar_sync(5 + s, NTHREADS);   // wait stage FREE

            // ---- B: cp.async 4 rows x 8 units into stage s ----
            {
                const uint32_t bb = st + A_SZ;
#pragma unroll
                for (int rb = 0; rb < 4; ++rb) {
                    int n = 4 * p + rb;
                    const __nv_bfloat16* src = g_wq + (size_t)n * K_TOTAL
                                               + kc * CHUNK_K;
                    uint32_t drow = bb + (uint32_t)(n * 128);
                    uint32_t key  = (uint32_t)(n & 7) << 4;
#pragma unroll
                    for (int j = 0; j < 8; ++j)
                        cp_async16(drow + (((uint32_t)j << 4) ^ key), src + j * 8);
                }
                cp_commit();
            }

            // ---- A: gather + quantize two rows ----
            const int t0 = kc % 9;
            const int c0 = (kc * 64) / 9;
#pragma unroll
            for (int h = 0; h < 2; ++h) {
                const int r = p + h * 64;
                const float* pix = pbase[h] + (size_t)c0 * IMG_PIX;
                float v[64];
                float mx = 0.0f;
                switch (t0) {
                    case 0: gather64<0>(pix, vmask[h], v, mx); break;
                    case 1: gather64<1>(pix, vmask[h], v, mx); break;
                    case 2: gather64<2>(pix, vmask[h], v, mx); break;
                    case 3: gather64<3>(pix, vmask[h], v, mx); break;
                    case 4: gather64<4>(pix, vmask[h], v, mx); break;
                    case 5: gather64<5>(pix, vmask[h], v, mx); break;
                    case 6: gather64<6>(pix, vmask[h], v, mx); break;
                    case 7: gather64<7>(pix, vmask[h], v, mx); break;
                    default: gather64<8>(pix, vmask[h], v, mx); break;
                }
                int e = block_exp(mx);
                float scale = __int_as_float((e + 121) << 23);
                float inv   = __int_as_float((133 - e) << 23);
                const uint32_t arow = st + (uint32_t)(r * 128);
                const uint32_t key  = (uint32_t)(r & 7) << 4;
#pragma unroll
                for (int i = 0; i < 32; ++i) {
                    __nv_bfloat162 pr = __floats2bfloat162_rn(
                        bfpq(v[2 * i], inv, scale), bfpq(v[2 * i + 1], inv, scale));
                    uint32_t addr = arow + ((((uint32_t)(i >> 2) << 4) ^ key)
                                            | ((uint32_t)(i & 3) << 2));
                    asm volatile("st.shared.b32 [%0], %1;"
                                 :: "r"(addr), "r"(*reinterpret_cast<uint32_t*>(&pr)));
                }
            }

            cp_wait<0>();          // B landed
            membar_cta();          // STS visible
            bar_arrive(1 + s, NTHREADS);   // stage FULL
        }
        return;
    }

    // ======================= CONSUMER (16 warps, 512 threads) ===============
    const int wid  = tid >> 5;
    const int lane = tid & 31;
    const int warp_m = wid & 3;
    const int warp_n = wid >> 2;

    // ldmatrix identities
    const int arow = warp_m * 32 + (lane & 15);
    const uint32_t akey  = (uint32_t)(arow & 7) << 4;
    const uint32_t abase = (uint32_t)(arow * 128);
    const uint32_t ahi   = (uint32_t)(lane >> 4) << 4;

    const int nrow = warp_n * 64 + ((lane >> 4) * 8) + (lane & 7);
    const uint32_t bkey  = (uint32_t)(nrow & 7) << 4;
    const uint32_t bbase = (uint32_t)(A_SZ + nrow * 128);
    const uint32_t bkub  = (uint32_t)((lane >> 3) & 1) << 4;

    float acc[16][4];
#pragma unroll
    for (int i = 0; i < 16; ++i)
#pragma unroll
        for (int j = 0; j < 4; ++j) acc[i][j] = 0.0f;

    for (int kc = 0; kc < NUM_KB; ++kc) {
        const int s = kc & 3;
        const uint32_t sb = smem_u + s * STAGE_SZ;
        bar_sync(1 + s, NTHREADS);          // wait stage FULL

#pragma unroll
        for (int ks = 0; ks < 4; ++ks) {
            uint32_t a0[4], a1[4];
            const uint32_t au = (((uint32_t)(2 * ks) << 4) + ahi);
            ldsm_x4(a0, sb + abase + (au ^ akey));
            ldsm_x4(a1, sb + abase + 16 * 128 + (au ^ akey));
            const uint32_t bu = (((uint32_t)(2 * ks) << 4) + bkub) ^ bkey;
#pragma unroll
            for (int nt2 = 0; nt2 < 4; ++nt2) {
                uint32_t b4[4];
                ldsm_x4(b4, sb + bbase + nt2 * 16 * 128 + bu);
                mma_16816(acc[nt2 * 2],         a0, b4[0], b4[1]);
                mma_16816(acc[nt2 * 2 + 1],     a0, b4[2], b4[3]);
                mma_16816(acc[8 + nt2 * 2],     a1, b4[0], b4[1]);
                mma_16816(acc[8 + nt2 * 2 + 1], a1, b4[2], b4[3]);
            }
        }
        if (kc + NSTAGES < NUM_KB) bar_arrive(5 + s, NTHREADS);   // stage FREE
    }

    // ---- epilogue: transpose via SMEM, coalesced NCHW stores + bias ----
    bar_sync(9, NCONS);                    // all consumers past last MMA
    float* sC = reinterpret_cast<float*>(smem);
#pragma unroll
    for (int mt = 0; mt < 2; ++mt)
#pragma unroll
        for (int nt = 0; nt < 8; ++nt) {
            int rr = warp_m * 32 + mt * 16 + (lane >> 2);
            int cc = warp_n * 64 + nt * 8 + 2 * (lane & 3);
            float* f = acc[mt * 8 + nt];
            sC[cc * C_STRIDE + rr]           = f[0];
            sC[(cc + 1) * C_STRIDE + rr]     = f[1];
            sC[cc * C_STRIDE + rr + 8]       = f[2];
            sC[(cc + 1) * C_STRIDE + rr + 8] = f[3];
        }
    bar_sync(9, NCONS);

#pragma unroll
    for (int j = 0; j < 4; ++j) {
        int rr = j * 32 + lane;
        int mm = m_base + rr;
        int ni2 = mm / IMG_PIX;
        int pp  = mm - ni2 * IMG_PIX;
        float* ob = out + (size_t)ni2 * (C_OUT * IMG_PIX) + pp;
#pragma unroll 4
        for (int i = 0; i < 16; ++i) {
            int cl = wid * 16 + i;
            ob[(size_t)cl * IMG_PIX] = sC[cl * C_STRIDE + rr] + __ldg(bias + cl);
        }
    }
}

// ---------------------------------------------------------------------------
extern "C" void kernel_launch(void* const* d_in, const int* in_sizes, int n_in,
                              void* d_out, int out_size) {
    (void)in_sizes; (void)n_in; (void)out_size;
    const float* inp  = (const float*)d_in[0];
    const float* w    = (const float*)d_in[1];
    const float* bias = (const float*)d_in[2];
    float* out = (float*)d_out;

    cudaFuncSetAttribute(conv_fused_kernel,
                         cudaFuncAttributeMaxDynamicSharedMemorySize, SMEM_TOTAL);

    quant_w_kernel<<<dim3(18, 256, 1), 32>>>(w);
    conv_fused_kernel<<<GRID_M, NTHREADS, SMEM_TOTAL>>>(inp, bias, out);
}

// round 6
// speedup vs baseline: 1.3282x; 1.3282x over previous
#include <cuda_runtime.h>
#include <cuda_bf16.h>
#include <stdint.h>

// ============================================================================
// BFP8 quantized 3x3 conv (stride 1, pad 1) == GEMM M=100352, N=256, K=1152
// Round 6: split (quant_w, quant_a -> bf16 scratch, gemm).
// GEMM v2: 256-thread CTA, 128x128 tile, 3-stage cp.async, 96KB smem,
//          __launch_bounds__(256,2) -> 2 CTAs/SM for cross-CTA latency hiding.
// ============================================================================

#define C_IN      128
#define C_OUT     256
#define HWDIM     56
#define IMG_PIX   3136
#define K_TOTAL   1152
#define M_TOTAL   100352
#define GRID_M    784

__device__ __align__(16) __nv_bfloat16 g_wq[C_OUT * K_TOTAL];
__device__ __align__(16) __nv_bfloat16 g_qa[(size_t)M_TOTAL * K_TOTAL]; // 231 MB

// ---------------------------------------------------------------------------
__device__ __forceinline__ uint32_t cvta_smem(const void* p) {
    uint32_t a;
    asm("{ .reg .u64 t; cvta.to.shared.u64 t, %1; cvt.u32.u64 %0, t; }"
        : "=r"(a) : "l"(p));
    return a;
}
__device__ __forceinline__ void ldsm_x4(uint32_t* d, uint32_t addr) {
    asm volatile("ldmatrix.sync.aligned.m8n8.x4.shared.b16 {%0,%1,%2,%3}, [%4];"
                 : "=r"(d[0]), "=r"(d[1]), "=r"(d[2]), "=r"(d[3]) : "r"(addr));
}
__device__ __forceinline__ void mma_16816(float* c, const uint32_t* a,
                                          uint32_t b0, uint32_t b1) {
    asm volatile(
        "mma.sync.aligned.m16n8k16.row.col.f32.bf16.bf16.f32 "
        "{%0,%1,%2,%3}, {%4,%5,%6,%7}, {%8,%9}, {%0,%1,%2,%3};"
        : "+f"(c[0]), "+f"(c[1]), "+f"(c[2]), "+f"(c[3])
        : "r"(a[0]), "r"(a[1]), "r"(a[2]), "r"(a[3]), "r"(b0), "r"(b1));
}
__device__ __forceinline__ void cp_async16(uint32_t dst, const void* src) {
    asm volatile("cp.async.cg.shared.global [%0], [%1], 16;" :: "r"(dst), "l"(src));
}
__device__ __forceinline__ void cp_commit() {
    asm volatile("cp.async.commit_group;");
}
template <int N>
__device__ __forceinline__ void cp_wait() {
    asm volatile("cp.async.wait_group %0;" :: "n"(N));
}

__device__ __forceinline__ int block_exp(float mx) {
    mx = fmaxf(mx, 1e-38f);
    return ((__float_as_int(mx) >> 23) & 255) - 127;
}
__device__ __forceinline__ float bfpq(float x, float inv, float scale) {
    float q = rintf(x * inv);
    q = fminf(q, 127.0f);
    return q * scale;
}

// ---------------------------------------------------------------------------
// Kernel 0: quantize weight -> bf16 g_wq
// ---------------------------------------------------------------------------
__global__ void quant_w_kernel(const float* __restrict__ w) {
    int row = blockIdx.y, blk = blockIdx.x, lane = threadIdx.x;
    int base = row * K_TOTAL + blk * 64;
    float a = w[base + lane];
    float b = w[base + 32 + lane];
    float mx = fmaxf(fabsf(a), fabsf(b));
#pragma unroll
    for (int o = 16; o > 0; o >>= 1)
        mx = fmaxf(mx, __shfl_xor_sync(0xFFFFFFFFu, mx, o));
    int e = block_exp(mx);
    float scale = __int_as_float((e + 121) << 23);
    float inv   = __int_as_float((133 - e) << 23);
    g_wq[base + lane]      = __float2bfloat16(bfpq(a, inv, scale));
    g_wq[base + 32 + lane] = __float2bfloat16(bfpq(b, inv, scale));
}

// ---------------------------------------------------------------------------
// Kernel 1: quantize im2col(A) -> g_qa  (grid 784 x 18, 256 threads)
// ---------------------------------------------------------------------------
template <int S>
__device__ __forceinline__ void gather32(const float* __restrict__ pix,
                                         uint32_t vmask, float* v, float& mx) {
#pragma unroll
    for (int e = 0; e < 32; ++e) {
        const int u   = S + e;
        const int ci  = u / 9;
        const int tap = u % 9;
        const int off = ci * IMG_PIX + (tap / 3) * HWDIM + (tap % 3);
        float val = ((vmask >> tap) & 1u) ? __ldg(pix + off) : 0.0f;
        v[e] = val;
        mx = fmaxf(mx, fabsf(val));
    }
}

__global__ void quant_a_kernel(const float* __restrict__ inp) {
    __shared__ float smax[256];
    const int tid  = threadIdx.x;
    const int r    = tid & 127;
    const int half = tid >> 7;
    const int m  = blockIdx.x * 128 + r;
    const int b  = blockIdx.y;
    const int t0 = b % 9;
    const int c0 = (64 * b) / 9;

    const int ni = m / IMG_PIX;
    const int p  = m - ni * IMG_PIX;
    const int ho = p / HWDIM;
    const int wo = p - ho * HWDIM;
    const float* pix = inp + ((size_t)ni * C_IN + c0) * IMG_PIX
                       + ho * HWDIM + wo - 57;

    uint32_t vmask = 0;
#pragma unroll
    for (int kh = 0; kh < 3; ++kh)
#pragma unroll
        for (int kw = 0; kw < 3; ++kw) {
            int h = ho + kh - 1, w = wo + kw - 1;
            if ((unsigned)h < (unsigned)HWDIM && (unsigned)w < (unsigned)HWDIM)
                vmask |= 1u << (kh * 3 + kw);
        }

    float v[32];
    float mx = 0.0f;
    switch (t0) {
        case 0: if (half) gather32<32>(pix, vmask, v, mx); else gather32<0>(pix, vmask, v, mx); break;
        case 1: if (half) gather32<33>(pix, vmask, v, mx); else gather32<1>(pix, vmask, v, mx); break;
        case 2: if (half) gather32<34>(pix, vmask, v, mx); else gather32<2>(pix, vmask, v, mx); break;
        case 3: if (half) gather32<35>(pix, vmask, v, mx); else gather32<3>(pix, vmask, v, mx); break;
        case 4: if (half) gather32<36>(pix, vmask, v, mx); else gather32<4>(pix, vmask, v, mx); break;
        case 5: if (half) gather32<37>(pix, vmask, v, mx); else gather32<5>(pix, vmask, v, mx); break;
        case 6: if (half) gather32<38>(pix, vmask, v, mx); else gather32<6>(pix, vmask, v, mx); break;
        case 7: if (half) gather32<39>(pix, vmask, v, mx); else gather32<7>(pix, vmask, v, mx); break;
        default:if (half) gather32<40>(pix, vmask, v, mx); else gather32<8>(pix, vmask, v, mx); break;
    }

    smax[tid] = mx;
    __syncthreads();
    mx = fmaxf(mx, smax[tid ^ 128]);

    int e = block_exp(mx);
    float scale = __int_as_float((e + 121) << 23);
    float inv   = __int_as_float((133 - e) << 23);

    uint32_t pk[16];
#pragma unroll
    for (int i = 0; i < 16; ++i) {
        __nv_bfloat162 pr = __floats2bfloat162_rn(bfpq(v[2 * i],     inv, scale),
                                                  bfpq(v[2 * i + 1], inv, scale));
        pk[i] = *reinterpret_cast<uint32_t*>(&pr);
    }
    uint4* dst = reinterpret_cast<uint4*>(g_qa + (size_t)m * K_TOTAL
                                          + b * 64 + half * 32);
#pragma unroll
    for (int i = 0; i < 4; ++i)
        dst[i] = make_uint4(pk[4 * i], pk[4 * i + 1], pk[4 * i + 2], pk[4 * i + 3]);
}

// ---------------------------------------------------------------------------
// Kernel 2: bf16 GEMM, tile 128x128, 256 threads (8 warps, 4x2), CHUNK_K=64,
// 3-stage cp.async (32KB/stage, 96KB total) -> 2 CTAs/SM.
// ---------------------------------------------------------------------------
#define K2_CHUNK   64
#define K2_NCHUNK  18
#define K2_A_SZ    16384              // 128 rows * 128B
#define K2_B_SZ    16384              // 128 rows * 128B
#define K2_STAGE   (K2_A_SZ + K2_B_SZ)      // 32768
#define K2_SMEM    (3 * K2_STAGE)           // 98304
#define C_STRIDE   132

__global__ __launch_bounds__(256, 2)
void gemm_kernel(const float* __restrict__ bias, float* __restrict__ out) {
    extern __shared__ __align__(16) char smem[];
    const uint32_t smem_u = cvta_smem(smem);

    const int tid  = threadIdx.x;
    const int wid  = tid >> 5;
    const int lane = tid & 31;
    const int warp_m = wid & 3;
    const int warp_n = wid >> 2;
    const int m_base = blockIdx.x * 128;
    const int ntile  = blockIdx.y;

    // ---- cp.async identities: thread loads 4x16B of A and 4x16B of B ----
    const int lrow = tid >> 1;              // 0..127
    const int jhalf = (tid & 1) * 4;        // units 0..3 or 4..7
    const uint32_t lkey = (uint32_t)(lrow & 7) << 4;
    const __nv_bfloat16* a_src = g_qa + (size_t)(m_base + lrow) * K_TOTAL
                                 + jhalf * 8;
    const __nv_bfloat16* b_src = g_wq + (size_t)(ntile * 128 + lrow) * K_TOTAL
                                 + jhalf * 8;
    const uint32_t a_dst = (uint32_t)(lrow * 128);
    const uint32_t b_dst = (uint32_t)(K2_A_SZ + lrow * 128);

    auto load_stage = [&](int kc, int s) {
        const uint32_t st = smem_u + s * K2_STAGE;
        const __nv_bfloat16* as = a_src + kc * K2_CHUNK;
        const __nv_bfloat16* bs = b_src + kc * K2_CHUNK;
#pragma unroll
        for (int i = 0; i < 4; ++i) {
            uint32_t j = (uint32_t)(jhalf + i);
            uint32_t sw = (j << 4) ^ lkey;
            cp_async16(st + a_dst + sw, as + i * 8);
            cp_async16(st + b_dst + sw, bs + i * 8);
        }
        cp_commit();
    };

    // ---- ldmatrix identities ----
    const int arow = warp_m * 32 + (lane & 15);
    const uint32_t akey  = (uint32_t)(arow & 7) << 4;
    const uint32_t abase = (uint32_t)(arow * 128);
    const uint32_t ahi   = (uint32_t)(lane >> 4) << 4;

    const int nrow = warp_n * 64 + ((lane >> 4) * 8) + (lane & 7);
    const uint32_t bkey  = (uint32_t)(nrow & 7) << 4;
    const uint32_t bbase = (uint32_t)(K2_A_SZ + nrow * 128);
    const uint32_t bkub  = (uint32_t)((lane >> 3) & 1) << 4;

    float acc[16][4];
#pragma unroll
    for (int i = 0; i < 16; ++i)
#pragma unroll
        for (int j = 0; j < 4; ++j) acc[i][j] = 0.0f;

    // ---- 3-stage pipeline ----
    load_stage(0, 0);
    load_stage(1, 1);

    int s = 0;
    for (int kc = 0; kc < K2_NCHUNK; ++kc) {
        if (kc + 1 < K2_NCHUNK) cp_wait<1>(); else cp_wait<0>();
        __syncthreads();
        const uint32_t sb = smem_u + s * K2_STAGE;

#pragma unroll
        for (int ks = 0; ks < 4; ++ks) {
            uint32_t a0[4], a1[4];
            const uint32_t au = (((uint32_t)(2 * ks) << 4) + ahi);
            ldsm_x4(a0, sb + abase + (au ^ akey));
            ldsm_x4(a1, sb + abase + 16 * 128 + (au ^ akey));
            const uint32_t bu = (((uint32_t)(2 * ks) << 4) + bkub) ^ bkey;
#pragma unroll
            for (int nt2 = 0; nt2 < 4; ++nt2) {
                uint32_t b4[4];
                ldsm_x4(b4, sb + bbase + nt2 * 16 * 128 + bu);
                mma_16816(acc[nt2 * 2],         a0, b4[0], b4[1]);
                mma_16816(acc[nt2 * 2 + 1],     a0, b4[2], b4[3]);
                mma_16816(acc[8 + nt2 * 2],     a1, b4[0], b4[1]);
                mma_16816(acc[8 + nt2 * 2 + 1], a1, b4[2], b4[3]);
            }
        }
        // next load goes into the stage freed at kc-1 (guarded by the next
        // iteration's __syncthreads for cross-warp safety)
        if (kc + 2 < K2_NCHUNK) load_stage(kc + 2, (s + 2 >= 3) ? s - 1 : s + 2);
        if (++s == 3) s = 0;
    }

    // ---- epilogue: transpose via SMEM, coalesced NCHW stores + bias ----
    __syncthreads();
    float* sC = reinterpret_cast<float*>(smem);
#pragma unroll
    for (int mt = 0; mt < 2; ++mt)
#pragma unroll
        for (int nt = 0; nt < 8; ++nt) {
            int rr = warp_m * 32 + mt * 16 + (lane >> 2);
            int cc = warp_n * 64 + nt * 8 + 2 * (lane & 3);
            float* f = acc[mt * 8 + nt];
            sC[cc * C_STRIDE + rr]           = f[0];
            sC[(cc + 1) * C_STRIDE + rr]     = f[1];
            sC[cc * C_STRIDE + rr + 8]       = f[2];
            sC[(cc + 1) * C_STRIDE + rr + 8] = f[3];
        }
    __syncthreads();

#pragma unroll
    for (int j = 0; j < 4; ++j) {
        int rr = j * 32 + lane;
        int mm = m_base + rr;
        int ni2 = mm / IMG_PIX;
        int pp  = mm - ni2 * IMG_PIX;
        float* ob = out + (size_t)ni2 * (C_OUT * IMG_PIX) + pp;
#pragma unroll 4
        for (int i = 0; i < 16; ++i) {
            int cl = wid * 16 + i;
            int co = ntile * 128 + cl;
            ob[(size_t)co * IMG_PIX] = sC[cl * C_STRIDE + rr] + __ldg(bias + co);
        }
    }
}

// ---------------------------------------------------------------------------
extern "C" void kernel_launch(void* const* d_in, const int* in_sizes, int n_in,
                              void* d_out, int out_size) {
    (void)in_sizes; (void)n_in; (void)out_size;
    const float* inp  = (const float*)d_in[0];
    const float* w    = (const float*)d_in[1];
    const float* bias = (const float*)d_in[2];
    float* out = (float*)d_out;

    cudaFuncSetAttribute(gemm_kernel,
                         cudaFuncAttributeMaxDynamicSharedMemorySize, K2_SMEM);

    quant_w_kernel<<<dim3(18, 256, 1), 32>>>(w);
    quant_a_kernel<<<dim3(GRID_M, 18, 1), 256>>>(inp);
    gemm_kernel<<<dim3(GRID_M, 2, 1), 256, K2_SMEM>>>(bias, out);
}

// round 7
// speedup vs baseline: 1.5273x; 1.1499x over previous
#include <cuda_runtime.h>
#include <cuda_bf16.h>
#include <stdint.h>

// ============================================================================
// BFP8 quantized 3x3 conv (stride 1, pad 1) == GEMM M=100352, N=256, K=1152
// Round 7: int8 path. Mantissas are exact s8; per-64-block pow2 scales.
//   K1: quantize weight -> g_wq8 (s8) + g_sw (f32 scales)
//   K2: quantize im2col(A) -> g_qa8 (s8, 110MB) + g_sa (f32 scales)
//   K3: s8 IMMA GEMM (mma.sync.m16n8k32) with per-block fp32 scale flush.
// ============================================================================

#define C_IN      128
#define C_OUT     256
#define HWDIM     56
#define IMG_PIX   3136
#define K_TOTAL   1152
#define M_TOTAL   100352
#define GRID_M    784
#define NBLK      18                   // 64-wide BFP blocks along K

__device__ __align__(16) int8_t g_wq8[C_OUT * K_TOTAL];
__device__ float   g_sw[NBLK * C_OUT];                   // [b][n]
__device__ __align__(16) int8_t g_qa8[(size_t)M_TOTAL * K_TOTAL];   // 110 MB
__device__ float   g_sa[(size_t)NBLK * M_TOTAL];         // [b][m], 7.2 MB

// ---------------------------------------------------------------------------
__device__ __forceinline__ uint32_t cvta_smem(const void* p) {
    uint32_t a;
    asm("{ .reg .u64 t; cvta.to.shared.u64 t, %1; cvt.u32.u64 %0, t; }"
        : "=r"(a) : "l"(p));
    return a;
}
__device__ __forceinline__ void ldsm_x4(uint32_t* d, uint32_t addr) {
    asm volatile("ldmatrix.sync.aligned.m8n8.x4.shared.b16 {%0,%1,%2,%3}, [%4];"
                 : "=r"(d[0]), "=r"(d[1]), "=r"(d[2]), "=r"(d[3]) : "r"(addr));
}
__device__ __forceinline__ void imma_init(int* d, const uint32_t* a,
                                          uint32_t b0, uint32_t b1) {
    asm volatile(
        "mma.sync.aligned.m16n8k32.row.col.s32.s8.s8.s32 "
        "{%0,%1,%2,%3}, {%4,%5,%6,%7}, {%8,%9}, {%10,%10,%10,%10};"
        : "=r"(d[0]), "=r"(d[1]), "=r"(d[2]), "=r"(d[3])
        : "r"(a[0]), "r"(a[1]), "r"(a[2]), "r"(a[3]),
          "r"(b0), "r"(b1), "r"(0));
}
__device__ __forceinline__ void imma_acc(int* d, const uint32_t* a,
                                         uint32_t b0, uint32_t b1) {
    asm volatile(
        "mma.sync.aligned.m16n8k32.row.col.s32.s8.s8.s32 "
        "{%0,%1,%2,%3}, {%4,%5,%6,%7}, {%8,%9}, {%0,%1,%2,%3};"
        : "+r"(d[0]), "+r"(d[1]), "+r"(d[2]), "+r"(d[3])
        : "r"(a[0]), "r"(a[1]), "r"(a[2]), "r"(a[3]), "r"(b0), "r"(b1));
}
__device__ __forceinline__ void cp_async16(uint32_t dst, const void* src) {
    asm volatile("cp.async.cg.shared.global [%0], [%1], 16;" :: "r"(dst), "l"(src));
}
__device__ __forceinline__ void cp_commit() {
    asm volatile("cp.async.commit_group;");
}
template <int N>
__device__ __forceinline__ void cp_wait() {
    asm volatile("cp.async.wait_group %0;" :: "n"(N));
}

__device__ __forceinline__ int block_exp(float mx) {
    mx = fmaxf(mx, 1e-38f);
    return ((__float_as_int(mx) >> 23) & 255) - 127;
}
// integer mantissa in [-128, 127] (low clamp impossible; see analysis)
__device__ __forceinline__ int qint(float x, float inv) {
    float q = rintf(x * inv);
    q = fminf(q, 127.0f);
    return (int)q;
}
__device__ __forceinline__ uint32_t pack4(int i0, int i1, int i2, int i3) {
    return (uint32_t)(i0 & 0xff) | ((uint32_t)(i1 & 0xff) << 8)
         | ((uint32_t)(i2 & 0xff) << 16) | ((uint32_t)i3 << 24);
}

// ---------------------------------------------------------------------------
// Kernel 1: quantize weight -> s8 + scales. <<<18, 256>>> (b = blockIdx.x)
// ---------------------------------------------------------------------------
__global__ void quant_w8_kernel(const float* __restrict__ w) {
    const int b   = blockIdx.x;
    const int row = threadIdx.x;
    const float* src = w + (size_t)row * K_TOTAL + b * 64;

    float v[64];
    float mx = 0.0f;
#pragma unroll 16
    for (int i = 0; i < 64; ++i) {
        v[i] = __ldg(src + i);
        mx = fmaxf(mx, fabsf(v[i]));
    }
    int e = block_exp(mx);
    float scale = __int_as_float((e + 121) << 23);   // 2^(e-6)
    float inv   = __int_as_float((133 - e) << 23);   // 2^(6-e)

    uint32_t pk[16];
#pragma unroll
    for (int i = 0; i < 16; ++i)
        pk[i] = pack4(qint(v[4*i], inv),   qint(v[4*i+1], inv),
                      qint(v[4*i+2], inv), qint(v[4*i+3], inv));
    uint4* dst = reinterpret_cast<uint4*>(g_wq8 + (size_t)row * K_TOTAL + b * 64);
#pragma unroll
    for (int i = 0; i < 4; ++i)
        dst[i] = make_uint4(pk[4*i], pk[4*i+1], pk[4*i+2], pk[4*i+3]);
    g_sw[b * C_OUT + row] = scale;
}

// ---------------------------------------------------------------------------
// Kernel 2: quantize im2col(A) -> s8 + scales. grid(784, 18), 256 threads.
// ---------------------------------------------------------------------------
template <int S>
__device__ __forceinline__ void gather32(const float* __restrict__ pix,
                                         uint32_t vmask, float* v, float& mx) {
#pragma unroll
    for (int e = 0; e < 32; ++e) {
        const int u   = S + e;
        const int ci  = u / 9;
        const int tap = u % 9;
        const int off = ci * IMG_PIX + (tap / 3) * HWDIM + (tap % 3);
        float val = ((vmask >> tap) & 1u) ? __ldg(pix + off) : 0.0f;
        v[e] = val;
        mx = fmaxf(mx, fabsf(val));
    }
}

__global__ void quant_a8_kernel(const float* __restrict__ inp) {
    __shared__ float smax[256];
    const int tid  = threadIdx.x;
    const int r    = tid & 127;
    const int half = tid >> 7;
    const int m  = blockIdx.x * 128 + r;
    const int b  = blockIdx.y;
    const int t0 = b % 9;
    const int c0 = (64 * b) / 9;

    const int ni = m / IMG_PIX;
    const int p  = m - ni * IMG_PIX;
    const int ho = p / HWDIM;
    const int wo = p - ho * HWDIM;
    const float* pix = inp + ((size_t)ni * C_IN + c0) * IMG_PIX
                       + ho * HWDIM + wo - 57;

    uint32_t vmask = 0;
#pragma unroll
    for (int kh = 0; kh < 3; ++kh)
#pragma unroll
        for (int kw = 0; kw < 3; ++kw) {
            int h = ho + kh - 1, w = wo + kw - 1;
            if ((unsigned)h < (unsigned)HWDIM && (unsigned)w < (unsigned)HWDIM)
                vmask |= 1u << (kh * 3 + kw);
        }

    float v[32];
    float mx = 0.0f;
    switch (t0) {
        case 0: if (half) gather32<32>(pix, vmask, v, mx); else gather32<0>(pix, vmask, v, mx); break;
        case 1: if (half) gather32<33>(pix, vmask, v, mx); else gather32<1>(pix, vmask, v, mx); break;
        case 2: if (half) gather32<34>(pix, vmask, v, mx); else gather32<2>(pix, vmask, v, mx); break;
        case 3: if (half) gather32<35>(pix, vmask, v, mx); else gather32<3>(pix, vmask, v, mx); break;
        case 4: if (half) gather32<36>(pix, vmask, v, mx); else gather32<4>(pix, vmask, v, mx); break;
        case 5: if (half) gather32<37>(pix, vmask, v, mx); else gather32<5>(pix, vmask, v, mx); break;
        case 6: if (half) gather32<38>(pix, vmask, v, mx); else gather32<6>(pix, vmask, v, mx); break;
        case 7: if (half) gather32<39>(pix, vmask, v, mx); else gather32<7>(pix, vmask, v, mx); break;
        default:if (half) gather32<40>(pix, vmask, v, mx); else gather32<8>(pix, vmask, v, mx); break;
    }

    smax[tid] = mx;
    __syncthreads();
    mx = fmaxf(mx, smax[tid ^ 128]);

    int e = block_exp(mx);
    float scale = __int_as_float((e + 121) << 23);
    float inv   = __int_as_float((133 - e) << 23);

    uint32_t pk[8];
#pragma unroll
    for (int i = 0; i < 8; ++i)
        pk[i] = pack4(qint(v[4*i], inv),   qint(v[4*i+1], inv),
                      qint(v[4*i+2], inv), qint(v[4*i+3], inv));
    uint4* dst = reinterpret_cast<uint4*>(g_qa8 + (size_t)m * K_TOTAL
                                          + b * 64 + half * 32);
    dst[0] = make_uint4(pk[0], pk[1], pk[2], pk[3]);
    dst[1] = make_uint4(pk[4], pk[5], pk[6], pk[7]);
    if (half == 0) g_sa[(size_t)b * M_TOTAL + m] = scale;
}

// ---------------------------------------------------------------------------
// Kernel 3: s8 GEMM. Tile 128x256, 512 threads (16 warps 4x4), warp 32x64.
// CHUNK_K = 128 s8 (2 BFP blocks) per stage; 9 stages; 4-deep cp.async ring.
// ---------------------------------------------------------------------------
#define A_SZ      16384                 // 128 rows * 128B
#define B_SZ      32768                 // 256 rows * 128B
#define STAGE     (A_SZ + B_SZ)         // 49152
#define NSTAGE    4
#define SCALE_OFF (NSTAGE * STAGE)      // 196608
#define SA_WORDS  (NBLK * 128)          // 2304
#define SW_WORDS  (NBLK * 256)          // 4608
#define K3_SMEM   (SCALE_OFF + 4 * (SA_WORDS + SW_WORDS))   // 224256
#define C_STRIDE  132

__global__ __launch_bounds__(512, 1)
void gemm8_kernel(const float* __restrict__ bias, float* __restrict__ out) {
    extern __shared__ __align__(16) char smem[];
    const uint32_t smem_u = cvta_smem(smem);
    float* sSA = reinterpret_cast<float*>(smem + SCALE_OFF);
    float* sSW = sSA + SA_WORDS;

    const int tid  = threadIdx.x;
    const int wid  = tid >> 5;
    const int lane = tid & 31;
    const int warp_m = wid & 3;
    const int warp_n = wid >> 2;
    const int m_base = blockIdx.x * 128;

    // ---- preload scales into SMEM ----
    for (int i = tid; i < SA_WORDS; i += 512)
        sSA[i] = g_sa[(size_t)(i >> 7) * M_TOTAL + m_base + (i & 127)];
    for (int i = tid; i < SW_WORDS; i += 512)
        sSW[i] = g_sw[i];

    // ---- cp.async identities: row = tid>>2, unit jj & jj+4 ----
    const int lr = tid >> 2;
    const int jj = tid & 3;
    const uint32_t lkey = (uint32_t)(lr & 7);
    const int8_t* a_src = g_qa8 + (size_t)(m_base + lr) * K_TOTAL;
    const int8_t* b_src = g_wq8 + (size_t)lr * K_TOTAL;
    const int8_t* b_src2 = g_wq8 + (size_t)(lr + 128) * K_TOTAL;

    auto load_stage = [&](int kc, int s) {
        const uint32_t st = smem_u + s * STAGE;
        const int ko = kc * 128;
#pragma unroll
        for (int i = 0; i < 2; ++i) {
            uint32_t u = (uint32_t)(jj + i * 4);
            uint32_t sw = (u ^ lkey) << 4;
            cp_async16(st + (uint32_t)(lr * 128) + sw, a_src + ko + u * 16);
            cp_async16(st + A_SZ + (uint32_t)(lr * 128) + sw, b_src + ko + u * 16);
            cp_async16(st + A_SZ + (uint32_t)((lr + 128) * 128) + sw,
                       b_src2 + ko + u * 16);
        }
        cp_commit();
    };

    // ---- ldsm identities ----
    const uint32_t keyA = (uint32_t)(lane & 7);
    const uint32_t hiA  = (uint32_t)(lane >> 4);             // k 16B half
    const uint32_t baseA = (uint32_t)((warp_m * 32 + (lane & 7)
                                       + ((lane >> 3) & 1) * 8) * 128);
    const uint32_t hiB  = (uint32_t)((lane >> 3) & 1);
    const uint32_t baseB = (uint32_t)(A_SZ + (warp_n * 64 + (lane & 7)
                                              + (lane >> 4) * 8) * 128);
    const int rs0 = warp_m * 32 + (lane >> 2);
    const int cs0 = warp_n * 64 + 2 * (lane & 3);

    float acc[16][4];
#pragma unroll
    for (int i = 0; i < 16; ++i)
#pragma unroll
        for (int j = 0; j < 4; ++j) acc[i][j] = 0.0f;

    load_stage(0, 0);
    load_stage(1, 1);
    load_stage(2, 2);

    for (int kc = 0; kc < 9; ++kc) {
        cp_wait<2>();
        __syncthreads();
        const uint32_t sb = smem_u + (kc & 3) * STAGE;

#pragma unroll
        for (int blk = 0; blk < 2; ++blk) {
            const int gb = kc * 2 + blk;
            float sa0 = sSA[gb * 128 + rs0];
            float sa1 = sSA[gb * 128 + rs0 + 8];
            float sa2 = sSA[gb * 128 + rs0 + 16];
            float sa3 = sSA[gb * 128 + rs0 + 24];

            uint32_t a[2][2][4];
#pragma unroll
            for (int mt = 0; mt < 2; ++mt)
#pragma unroll
                for (int ks = 0; ks < 2; ++ks)
                    ldsm_x4(a[mt][ks], sb + baseA + mt * 2048
                            + ((((uint32_t)(blk * 4 + ks * 2) + hiA) ^ keyA) << 4));

#pragma unroll
            for (int ntp = 0; ntp < 4; ++ntp) {
                uint32_t b0[4], b1[4];
                ldsm_x4(b0, sb + baseB + ntp * 2048
                        + ((((uint32_t)(blk * 4) + hiB) ^ keyA) << 4));
                ldsm_x4(b1, sb + baseB + ntp * 2048
                        + ((((uint32_t)(blk * 4 + 2) + hiB) ^ keyA) << 4));
                const float sw0 = sSW[gb * 256 + cs0 + ntp * 16];
                const float sw1 = sSW[gb * 256 + cs0 + ntp * 16 + 1];
                const float sw2 = sSW[gb * 256 + cs0 + ntp * 16 + 8];
                const float sw3 = sSW[gb * 256 + cs0 + ntp * 16 + 9];
#pragma unroll
                for (int mt = 0; mt < 2; ++mt) {
                    const float ra = (mt == 0) ? sa0 : sa2;
                    const float rb = (mt == 0) ? sa1 : sa3;
#pragma unroll
                    for (int nf = 0; nf < 2; ++nf) {
                        int t[4];
                        imma_init(t, a[mt][0], b0[nf * 2], b0[nf * 2 + 1]);
                        imma_acc (t, a[mt][1], b1[nf * 2], b1[nf * 2 + 1]);
                        const float ca = nf ? sw2 : sw0;
                        const float cb = nf ? sw3 : sw1;
                        float* A_ = acc[mt * 8 + ntp * 2 + nf];
                        A_[0] += (ra * ca) * __int2float_rn(t[0]);
                        A_[1] += (ra * cb) * __int2float_rn(t[1]);
                        A_[2] += (rb * ca) * __int2float_rn(t[2]);
                        A_[3] += (rb * cb) * __int2float_rn(t[3]);
                    }
                }
            }
        }
        if (kc + 3 < 9) load_stage(kc + 3, (kc + 3) & 3);
        else cp_commit();
    }

    // ---- epilogue: transpose via SMEM, coalesced NCHW stores + bias ----
    __syncthreads();
    float* sC = reinterpret_cast<float*>(smem);
#pragma unroll
    for (int mt = 0; mt < 2; ++mt)
#pragma unroll
        for (int nt = 0; nt < 8; ++nt) {
            int rr = warp_m * 32 + mt * 16 + (lane >> 2);
            int cc = warp_n * 64 + nt * 8 + 2 * (lane & 3);
            float* f = acc[mt * 8 + nt];
            sC[cc * C_STRIDE + rr]           = f[0];
            sC[(cc + 1) * C_STRIDE + rr]     = f[1];
            sC[cc * C_STRIDE + rr + 8]       = f[2];
            sC[(cc + 1) * C_STRIDE + rr + 8] = f[3];
        }
    __syncthreads();

#pragma unroll
    for (int j = 0; j < 4; ++j) {
        int rr = j * 32 + lane;
        int mm = m_base + rr;
        int ni2 = mm / IMG_PIX;
        int pp  = mm - ni2 * IMG_PIX;
        float* ob = out + (size_t)ni2 * (C_OUT * IMG_PIX) + pp;
#pragma unroll 4
        for (int i = 0; i < 16; ++i) {
            int cl = wid * 16 + i;
            ob[(size_t)cl * IMG_PIX] = sC[cl * C_STRIDE + rr] + __ldg(bias + cl);
        }
    }
}

// ---------------------------------------------------------------------------
extern "C" void kernel_launch(void* const* d_in, const int* in_sizes, int n_in,
                              void* d_out, int out_size) {
    (void)in_sizes; (void)n_in; (void)out_size;
    const float* inp  = (const float*)d_in[0];
    const float* w    = (const float*)d_in[1];
    const float* bias = (const float*)d_in[2];
    float* out = (float*)d_out;

    cudaFuncSetAttribute(gemm8_kernel,
                         cudaFuncAttributeMaxDynamicSharedMemorySize, K3_SMEM);

    quant_w8_kernel<<<NBLK, 256>>>(w);
    quant_a8_kernel<<<dim3(GRID_M, NBLK, 1), 256>>>(inp);
    gemm8_kernel<<<GRID_M, 512, K3_SMEM>>>(bias, out);
}

// round 8
// speedup vs baseline: 1.5841x; 1.0372x over previous
#include <cuda_runtime.h>
#include <cuda_bf16.h>
#include <stdint.h>

// ============================================================================
// BFP8 quantized 3x3 conv (stride 1, pad 1) == GEMM M=100352, N=256, K=1152
// Round 8: int8 IMMA path, occupancy-tuned GEMM.
//   K1: quantize weight -> s8 + scales (warp per 64-block)
//   K2: quantize im2col(A) -> s8 (110MB) + scales
//   K3: s8 GEMM 128x128 tile, 256 thr, 2-stage cp.async, 2 CTAs/SM.
// ============================================================================

#define C_IN      128
#define C_OUT     256
#define HWDIM     56
#define IMG_PIX   3136
#define K_TOTAL   1152
#define M_TOTAL   100352
#define GRID_M    784
#define NBLK      18

__device__ __align__(16) int8_t g_wq8[C_OUT * K_TOTAL];
__device__ float   g_sw[NBLK * C_OUT];                    // [b][n]
__device__ __align__(16) int8_t g_qa8[(size_t)M_TOTAL * K_TOTAL];   // 110 MB
__device__ float   g_sa[(size_t)NBLK * M_TOTAL];          // [b][m]

// ---------------------------------------------------------------------------
__device__ __forceinline__ uint32_t cvta_smem(const void* p) {
    uint32_t a;
    asm("{ .reg .u64 t; cvta.to.shared.u64 t, %1; cvt.u32.u64 %0, t; }"
        : "=r"(a) : "l"(p));
    return a;
}
__device__ __forceinline__ void ldsm_x4(uint32_t* d, uint32_t addr) {
    asm volatile("ldmatrix.sync.aligned.m8n8.x4.shared.b16 {%0,%1,%2,%3}, [%4];"
                 : "=r"(d[0]), "=r"(d[1]), "=r"(d[2]), "=r"(d[3]) : "r"(addr));
}
__device__ __forceinline__ void imma_init(int* d, const uint32_t* a,
                                          uint32_t b0, uint32_t b1) {
    asm volatile(
        "mma.sync.aligned.m16n8k32.row.col.s32.s8.s8.s32 "
        "{%0,%1,%2,%3}, {%4,%5,%6,%7}, {%8,%9}, {%10,%10,%10,%10};"
        : "=r"(d[0]), "=r"(d[1]), "=r"(d[2]), "=r"(d[3])
        : "r"(a[0]), "r"(a[1]), "r"(a[2]), "r"(a[3]),
          "r"(b0), "r"(b1), "r"(0));
}
__device__ __forceinline__ void imma_acc(int* d, const uint32_t* a,
                                         uint32_t b0, uint32_t b1) {
    asm volatile(
        "mma.sync.aligned.m16n8k32.row.col.s32.s8.s8.s32 "
        "{%0,%1,%2,%3}, {%4,%5,%6,%7}, {%8,%9}, {%0,%1,%2,%3};"
        : "+r"(d[0]), "+r"(d[1]), "+r"(d[2]), "+r"(d[3])
        : "r"(a[0]), "r"(a[1]), "r"(a[2]), "r"(a[3]), "r"(b0), "r"(b1));
}
__device__ __forceinline__ void cp_async16(uint32_t dst, const void* src) {
    asm volatile("cp.async.cg.shared.global [%0], [%1], 16;" :: "r"(dst), "l"(src));
}
__device__ __forceinline__ void cp_commit() {
    asm volatile("cp.async.commit_group;");
}
template <int N>
__device__ __forceinline__ void cp_wait() {
    asm volatile("cp.async.wait_group %0;" :: "n"(N));
}

__device__ __forceinline__ int block_exp(float mx) {
    mx = fmaxf(mx, 1e-38f);
    return ((__float_as_int(mx) >> 23) & 255) - 127;
}
__device__ __forceinline__ int qint(float x, float inv) {
    float q = rintf(x * inv);
    q = fminf(q, 127.0f);
    return (int)q;
}
__device__ __forceinline__ uint32_t pack4(int i0, int i1, int i2, int i3) {
    return (uint32_t)(i0 & 0xff) | ((uint32_t)(i1 & 0xff) << 8)
         | ((uint32_t)(i2 & 0xff) << 16) | ((uint32_t)i3 << 24);
}

// ---------------------------------------------------------------------------
// Kernel 1: quantize weight. One warp per (row, 64-block). grid (18, 256).
// ---------------------------------------------------------------------------
__global__ void quant_w8_kernel(const float* __restrict__ w) {
    const int b    = blockIdx.x;
    const int row  = blockIdx.y;
    const int lane = threadIdx.x;
    const float* src = w + (size_t)row * K_TOTAL + b * 64;

    float a0 = __ldg(src + lane);
    float a1 = __ldg(src + 32 + lane);
    float mx = fmaxf(fabsf(a0), fabsf(a1));
#pragma unroll
    for (int o = 16; o > 0; o >>= 1)
        mx = fmaxf(mx, __shfl_xor_sync(0xFFFFFFFFu, mx, o));
    int e = block_exp(mx);
    float scale = __int_as_float((e + 121) << 23);
    float inv   = __int_as_float((133 - e) << 23);
    int8_t* dst = g_wq8 + (size_t)row * K_TOTAL + b * 64;
    dst[lane]      = (int8_t)qint(a0, inv);
    dst[32 + lane] = (int8_t)qint(a1, inv);
    if (lane == 0) g_sw[b * C_OUT + row] = scale;
}

// ---------------------------------------------------------------------------
// Kernel 2: quantize im2col(A). grid (784, 18), 256 threads.
// ---------------------------------------------------------------------------
template <int S>
__device__ __forceinline__ void gather32(const float* __restrict__ pix,
                                         uint32_t vmask, float* v, float& mx) {
#pragma unroll
    for (int e = 0; e < 32; ++e) {
        const int u   = S + e;
        const int ci  = u / 9;
        const int tap = u % 9;
        const int off = ci * IMG_PIX + (tap / 3) * HWDIM + (tap % 3);
        float val = ((vmask >> tap) & 1u) ? __ldg(pix + off) : 0.0f;
        v[e] = val;
        mx = fmaxf(mx, fabsf(val));
    }
}

__global__ void quant_a8_kernel(const float* __restrict__ inp) {
    __shared__ float smax[256];
    const int tid  = threadIdx.x;
    const int r    = tid & 127;
    const int half = tid >> 7;
    const int m  = blockIdx.x * 128 + r;
    const int b  = blockIdx.y;
    const int t0 = b % 9;
    const int c0 = (64 * b) / 9;

    const int ni = m / IMG_PIX;
    const int p  = m - ni * IMG_PIX;
    const int ho = p / HWDIM;
    const int wo = p - ho * HWDIM;
    const float* pix = inp + ((size_t)ni * C_IN + c0) * IMG_PIX
                       + ho * HWDIM + wo - 57;

    uint32_t vmask = 0;
#pragma unroll
    for (int kh = 0; kh < 3; ++kh)
#pragma unroll
        for (int kw = 0; kw < 3; ++kw) {
            int h = ho + kh - 1, w = wo + kw - 1;
            if ((unsigned)h < (unsigned)HWDIM && (unsigned)w < (unsigned)HWDIM)
                vmask |= 1u << (kh * 3 + kw);
        }

    float v[32];
    float mx = 0.0f;
    switch (t0) {
        case 0: if (half) gather32<32>(pix, vmask, v, mx); else gather32<0>(pix, vmask, v, mx); break;
        case 1: if (half) gather32<33>(pix, vmask, v, mx); else gather32<1>(pix, vmask, v, mx); break;
        case 2: if (half) gather32<34>(pix, vmask, v, mx); else gather32<2>(pix, vmask, v, mx); break;
        case 3: if (half) gather32<35>(pix, vmask, v, mx); else gather32<3>(pix, vmask, v, mx); break;
        case 4: if (half) gather32<36>(pix, vmask, v, mx); else gather32<4>(pix, vmask, v, mx); break;
        case 5: if (half) gather32<37>(pix, vmask, v, mx); else gather32<5>(pix, vmask, v, mx); break;
        case 6: if (half) gather32<38>(pix, vmask, v, mx); else gather32<6>(pix, vmask, v, mx); break;
        case 7: if (half) gather32<39>(pix, vmask, v, mx); else gather32<7>(pix, vmask, v, mx); break;
        default:if (half) gather32<40>(pix, vmask, v, mx); else gather32<8>(pix, vmask, v, mx); break;
    }

    smax[tid] = mx;
    __syncthreads();
    mx = fmaxf(mx, smax[tid ^ 128]);

    int e = block_exp(mx);
    float scale = __int_as_float((e + 121) << 23);
    float inv   = __int_as_float((133 - e) << 23);

    uint32_t pk[8];
#pragma unroll
    for (int i = 0; i < 8; ++i)
        pk[i] = pack4(qint(v[4*i], inv),   qint(v[4*i+1], inv),
                      qint(v[4*i+2], inv), qint(v[4*i+3], inv));
    uint4* dst = reinterpret_cast<uint4*>(g_qa8 + (size_t)m * K_TOTAL
                                          + b * 64 + half * 32);
    dst[0] = make_uint4(pk[0], pk[1], pk[2], pk[3]);
    dst[1] = make_uint4(pk[4], pk[5], pk[6], pk[7]);
    if (half == 0) g_sa[(size_t)b * M_TOTAL + m] = scale;
}

// ---------------------------------------------------------------------------
// Kernel 3: s8 GEMM. Tile 128x128, 256 threads (8 warps 4x2), warp 32x64.
// CHUNK_K=128 (2 BFP blocks) per stage; 9 iters; 2-stage cp.async; 2 CTAs/SM.
// ---------------------------------------------------------------------------
#define A_SZ      16384                 // 128 rows * 128B
#define B_SZ      16384                 // 128 rows * 128B
#define STAGE     (A_SZ + B_SZ)         // 32768
#define SCALE_OFF (2 * STAGE)           // 65536
#define SA_WORDS  (NBLK * 128)          // 2304
#define SW_WORDS  (NBLK * 128)          // 2304
#define K3_SMEM   (SCALE_OFF + 4 * (SA_WORDS + SW_WORDS))   // 83968
#define C_STRIDE  132

__global__ __launch_bounds__(256, 2)
void gemm8_kernel(const float* __restrict__ bias, float* __restrict__ out) {
    extern __shared__ __align__(16) char smem[];
    const uint32_t smem_u = cvta_smem(smem);
    float* sSA = reinterpret_cast<float*>(smem + SCALE_OFF);
    float* sSW = sSA + SA_WORDS;

    const int tid  = threadIdx.x;
    const int wid  = tid >> 5;
    const int lane = tid & 31;
    const int warp_m = wid & 3;
    const int warp_n = wid >> 2;
    const int ntile  = blockIdx.x;           // 0..1
    const int m_base = blockIdx.y * 128;

    // ---- preload scales ----
    for (int i = tid; i < SA_WORDS; i += 256)
        sSA[i] = g_sa[(size_t)(i >> 7) * M_TOTAL + m_base + (i & 127)];
    for (int i = tid; i < SW_WORDS; i += 256)
        sSW[i] = g_sw[(i >> 7) * C_OUT + ntile * 128 + (i & 127)];

    // ---- cp.async identities: row lr = tid>>1, 4 units each half ----
    const int lr = tid >> 1;
    const int jh = (tid & 1) * 4;
    const uint32_t lkey = (uint32_t)(lr & 7);
    const int8_t* a_src = g_qa8 + (size_t)(m_base + lr) * K_TOTAL;
    const int8_t* b_src = g_wq8 + (size_t)(ntile * 128 + lr) * K_TOTAL;

    auto load_stage = [&](int kc, int s) {
        const uint32_t st = smem_u + s * STAGE;
        const int ko = kc * 128;
#pragma unroll
        for (int i = 0; i < 4; ++i) {
            uint32_t u = (uint32_t)(jh + i);
            uint32_t sw = ((u ^ lkey) << 4) + (uint32_t)(lr * 128);
            cp_async16(st + sw, a_src + ko + u * 16);
            cp_async16(st + A_SZ + sw, b_src + ko + u * 16);
        }
        cp_commit();
    };

    // ---- ldsm identities ----
    const uint32_t keyA = (uint32_t)(lane & 7);
    const uint32_t hiA  = (uint32_t)(lane >> 4);
    const uint32_t baseA = (uint32_t)((warp_m * 32 + (lane & 7)
                                       + ((lane >> 3) & 1) * 8) * 128);
    const uint32_t hiB  = (uint32_t)((lane >> 3) & 1);
    const uint32_t baseB = (uint32_t)(A_SZ + (warp_n * 64 + (lane & 7)
                                              + (lane >> 4) * 8) * 128);
    const int rs0 = warp_m * 32 + (lane >> 2);
    const int cs0 = warp_n * 64 + 2 * (lane & 3);

    float acc[16][4];
#pragma unroll
    for (int i = 0; i < 16; ++i)
#pragma unroll
        for (int j = 0; j < 4; ++j) acc[i][j] = 0.0f;

    load_stage(0, 0);

    for (int kc = 0; kc < 9; ++kc) {
        if (kc + 1 < 9) load_stage(kc + 1, (kc + 1) & 1);
        if (kc + 1 < 9) cp_wait<1>(); else cp_wait<0>();
        __syncthreads();
        const uint32_t sb = smem_u + (kc & 1) * STAGE;

#pragma unroll
        for (int blk = 0; blk < 2; ++blk) {
            const int gb = kc * 2 + blk;
            const float sa0 = sSA[gb * 128 + rs0];
            const float sa1 = sSA[gb * 128 + rs0 + 8];
            const float sa2 = sSA[gb * 128 + rs0 + 16];
            const float sa3 = sSA[gb * 128 + rs0 + 24];

            uint32_t a[2][2][4];
#pragma unroll
            for (int mt = 0; mt < 2; ++mt)
#pragma unroll
                for (int ks = 0; ks < 2; ++ks)
                    ldsm_x4(a[mt][ks], sb + baseA + mt * 2048
                            + ((((uint32_t)(blk * 4 + ks * 2) + hiA) ^ keyA) << 4));

#pragma unroll
            for (int ntp = 0; ntp < 4; ++ntp) {
                uint32_t b0[4], b1[4];
                ldsm_x4(b0, sb + baseB + ntp * 2048
                        + ((((uint32_t)(blk * 4) + hiB) ^ keyA) << 4));
                ldsm_x4(b1, sb + baseB + ntp * 2048
                        + ((((uint32_t)(blk * 4 + 2) + hiB) ^ keyA) << 4));
                const float sw0 = sSW[gb * 128 + cs0 + ntp * 16];
                const float sw1 = sSW[gb * 128 + cs0 + ntp * 16 + 1];
                const float sw2 = sSW[gb * 128 + cs0 + ntp * 16 + 8];
                const float sw3 = sSW[gb * 128 + cs0 + ntp * 16 + 9];
#pragma unroll
                for (int mt = 0; mt < 2; ++mt) {
                    const float ra = (mt == 0) ? sa0 : sa2;
                    const float rb = (mt == 0) ? sa1 : sa3;
#pragma unroll
                    for (int nf = 0; nf < 2; ++nf) {
                        int t[4];
                        imma_init(t, a[mt][0], b0[nf * 2], b0[nf * 2 + 1]);
                        imma_acc (t, a[mt][1], b1[nf * 2], b1[nf * 2 + 1]);
                        const float ca = nf ? sw2 : sw0;
                        const float cb = nf ? sw3 : sw1;
                        float* A_ = acc[mt * 8 + ntp * 2 + nf];
                        A_[0] += (ra * ca) * __int2float_rn(t[0]);
                        A_[1] += (ra * cb) * __int2float_rn(t[1]);
                        A_[2] += (rb * ca) * __int2float_rn(t[2]);
                        A_[3] += (rb * cb) * __int2float_rn(t[3]);
                    }
                }
            }
        }
        __syncthreads();    // stage consumed; next iteration may overwrite it
    }

    // ---- epilogue: transpose via SMEM, coalesced NCHW stores + bias ----
    float* sC = reinterpret_cast<float*>(smem);
#pragma unroll
    for (int mt = 0; mt < 2; ++mt)
#pragma unroll
        for (int nt = 0; nt < 8; ++nt) {
            int rr = warp_m * 32 + mt * 16 + (lane >> 2);
            int cc = warp_n * 64 + nt * 8 + 2 * (lane & 3);
            float* f = acc[mt * 8 + nt];
            sC[cc * C_STRIDE + rr]           = f[0];
            sC[(cc + 1) * C_STRIDE + rr]     = f[1];
            sC[cc * C_STRIDE + rr + 8]       = f[2];
            sC[(cc + 1) * C_STRIDE + rr + 8] = f[3];
        }
    __syncthreads();

#pragma unroll
    for (int j = 0; j < 4; ++j) {
        int rr = j * 32 + lane;
        int mm = m_base + rr;
        int ni2 = mm / IMG_PIX;
        int pp  = mm - ni2 * IMG_PIX;
        float* ob = out + (size_t)ni2 * (C_OUT * IMG_PIX) + pp;
#pragma unroll 4
        for (int i = 0; i < 16; ++i) {
            int cl = wid * 16 + i;
            int co = ntile * 128 + cl;
            ob[(size_t)co * IMG_PIX] = sC[cl * C_STRIDE + rr] + __ldg(bias + co);
        }
    }
}

// ---------------------------------------------------------------------------
extern "C" void kernel_launch(void* const* d_in, const int* in_sizes, int n_in,
                              void* d_out, int out_size) {
    (void)in_sizes; (void)n_in; (void)out_size;
    const float* inp  = (const float*)d_in[0];
    const float* w    = (const float*)d_in[1];
    const float* bias = (const float*)d_in[2];
    float* out = (float*)d_out;

    cudaFuncSetAttribute(gemm8_kernel,
                         cudaFuncAttributeMaxDynamicSharedMemorySize, K3_SMEM);

    quant_w8_kernel<<<dim3(NBLK, C_OUT, 1), 32>>>(w);
    quant_a8_kernel<<<dim3(GRID_M, NBLK, 1), 256>>>(inp);
    gemm8_kernel<<<dim3(2, GRID_M, 1), 256, K3_SMEM>>>(bias, out);
}